// round 1
// baseline (speedup 1.0000x reference)
#include <cuda_runtime.h>

// SpikeCNN fused kernel: one block = one image, all T=8 timesteps in SMEM/regs.
// conv1 is hoisted out of the time loop (input x is time-invariant).

#define TH 1.0f
#define TSTEPS 8
#define XP 33      // xpad row pitch (28+4 padded to 33 -> conflict-free strided rows)
#define C1P 29     // c1 / mem1 row pitch

__global__ __launch_bounds__(192, 2)
void snn_kernel(const float* __restrict__ x,
                const float* __restrict__ w1, const float* __restrict__ b1,
                const float* __restrict__ w2, const float* __restrict__ b2,
                const float* __restrict__ wf, const float* __restrict__ bf,
                float* __restrict__ out, int nb)
{
    __shared__ float xpad[32 * XP];        // 1056: zero-padded 28x28 input
    __shared__ float c1s[3 * 28 * C1P];    // 2436: conv1 output (time-invariant)
    __shared__ float mem1[3 * 28 * C1P];   // 2436
    __shared__ float p1pad[3 * 18 * 18];   // 972: pooled spikes of layer1, zero border
    __shared__ float s2s[6 * 196];         // 1176: layer-2 spikes
    __shared__ float p2s[294];             // pooled layer-2 spikes (fc input)
    __shared__ float w2s[450];
    __shared__ float fcsum[10];
    __shared__ float mem3[10], acc3[10];

    const int tid  = threadIdx.x;
    const int warp = tid >> 5;             // 0..5
    const int lane = tid & 31;
    const int b    = blockIdx.x;

    // ---- init ----
    for (int i = tid; i < 32 * XP; i += 192)     xpad[i]  = 0.f;
    for (int i = tid; i < 3 * 28 * C1P; i += 192) mem1[i] = 0.f;
    for (int i = tid; i < 3 * 18 * 18; i += 192) p1pad[i] = 0.f;
    for (int i = tid; i < 450; i += 192)         w2s[i]   = w2[i];
    if (tid < 10) { mem3[tid] = 0.f; acc3[tid] = 0.f; }
    __syncthreads();

    const float* xb = x + (size_t)b * 784;
    for (int i = tid; i < 784; i += 192) {
        int r = i / 28, c = i % 28;
        xpad[(r + 2) * XP + (c + 2)] = xb[i];
    }
    __syncthreads();

    // ---- conv1 (once): warp -> (channel = warp%3, col-half = warp/3), lane = row ----
    {
        int c = warp % 3, colbase = (warp / 3) * 14;
        if (lane < 28) {
            float wr[25];
            #pragma unroll
            for (int k = 0; k < 25; k++) wr[k] = __ldg(&w1[c * 25 + k]);
            float bias = __ldg(&b1[c]);
            float acc[14];
            #pragma unroll
            for (int j = 0; j < 14; j++) acc[j] = bias;
            int row = lane;
            #pragma unroll
            for (int di = 0; di < 5; di++) {
                float v[18];
                const float* src = &xpad[(row + di) * XP + colbase];
                #pragma unroll
                for (int k = 0; k < 18; k++) v[k] = src[k];
                #pragma unroll
                for (int j = 0; j < 14; j++)
                    #pragma unroll
                    for (int dj = 0; dj < 5; dj++)
                        acc[j] += v[j + dj] * wr[di * 5 + dj];
            }
            float* dst = &c1s[c * 28 * C1P + row * C1P + colbase];
            #pragma unroll
            for (int j = 0; j < 14; j++) dst[j] = acc[j];
        }
    }
    __syncthreads();

    // mem2 state lives in registers: warp = out-channel, lane<28 = (row, half-row)
    float m2r[7];
    #pragma unroll
    for (int j = 0; j < 7; j++) m2r[j] = 0.f;
    const float b2r = (lane < 28) ? __ldg(&b2[warp]) : 0.f;

    // ---- time loop ----
    for (int t = 0; t < TSTEPS; t++) {
        // A: mem1 += c1, fire, 2x2 avg-pool -> p1pad (one thread per pool group)
        for (int idx = tid; idx < 588; idx += 192) {
            int c = idx / 196, rem = idx % 196, pi = rem / 14, pj = rem % 14;
            int base = c * 28 * C1P + (2 * pi) * C1P + 2 * pj;
            float s = 0.f;
            #pragma unroll
            for (int a = 0; a < 2; a++)
                #pragma unroll
                for (int bb = 0; bb < 2; bb++) {
                    int off = base + a * C1P + bb;
                    float m = mem1[off] + c1s[off];
                    float sp = (m >= TH) ? TH : 0.f;
                    mem1[off] = m - sp;
                    s += sp;
                }
            p1pad[c * 324 + (pi + 2) * 18 + (pj + 2)] = s * 0.25f;
        }
        __syncthreads();

        // B: conv2 + mem2 fire. warp = oc; lane = half-row (7 outputs, reg window)
        if (lane < 28) {
            int oc = warp;
            int row = lane >> 1, colbase = (lane & 1) * 7;
            float acc[7];
            #pragma unroll
            for (int j = 0; j < 7; j++) acc[j] = b2r;   // bias added each step
            #pragma unroll
            for (int ic = 0; ic < 3; ic++) {
                float wr[25];
                #pragma unroll
                for (int k = 0; k < 25; k++) wr[k] = w2s[oc * 75 + ic * 25 + k];
                #pragma unroll
                for (int di = 0; di < 5; di++) {
                    float v[11];
                    const float* src = &p1pad[ic * 324 + (row + di) * 18 + colbase];
                    #pragma unroll
                    for (int k = 0; k < 11; k++) v[k] = src[k];
                    #pragma unroll
                    for (int j = 0; j < 7; j++)
                        #pragma unroll
                        for (int dj = 0; dj < 5; dj++)
                            acc[j] += v[j + dj] * wr[di * 5 + dj];
                }
            }
            float* s2dst = &s2s[oc * 196 + row * 14 + colbase];
            #pragma unroll
            for (int j = 0; j < 7; j++) {
                float m = m2r[j] + acc[j];
                float sp = (m >= TH) ? TH : 0.f;
                m2r[j] = m - sp;
                s2dst[j] = sp;
            }
        }
        __syncthreads();

        // C: 2x2 avg-pool layer 2 -> p2 (flatten order oc*49 + pi*7 + pj)
        for (int idx = tid; idx < 294; idx += 192) {
            int oc = idx / 49, rem = idx % 49, pi = rem / 7, pj = rem % 7;
            const float* sp = &s2s[oc * 196 + 2 * pi * 14 + 2 * pj];
            p2s[idx] = 0.25f * (sp[0] + sp[1] + sp[14] + sp[15]);
        }
        __syncthreads();

        // D: fc — warp w reduces output w (and w+6 if w<4)
        {
            float part = 0.f;
            const float* wrow = wf + warp * 294;
            for (int k = lane; k < 294; k += 32) part += p2s[k] * __ldg(&wrow[k]);
            #pragma unroll
            for (int s = 16; s > 0; s >>= 1) part += __shfl_xor_sync(0xffffffffu, part, s);
            if (lane == 0) fcsum[warp] = part;
            if (warp < 4) {
                float part2 = 0.f;
                const float* wrow2 = wf + (warp + 6) * 294;
                for (int k = lane; k < 294; k += 32) part2 += p2s[k] * __ldg(&wrow2[k]);
                #pragma unroll
                for (int s = 16; s > 0; s >>= 1) part2 += __shfl_xor_sync(0xffffffffu, part2, s);
                if (lane == 0) fcsum[warp + 6] = part2;
            }
        }
        __syncthreads();

        // E: mem3 update, fire, accumulate, emit running average at t=3,7
        if (tid < 10) {
            float m = mem3[tid] + fcsum[tid] + __ldg(&bf[tid]);
            float sp = (m >= TH) ? TH : 0.f;
            mem3[tid] = m - sp;
            float a = acc3[tid] + sp;
            acc3[tid] = a;
            if (t == 3) out[(size_t)b * 10 + tid] = a * 0.25f;
            if (t == 7) out[(size_t)nb * 10 + (size_t)b * 10 + tid] = a * 0.125f;
        }
        __syncthreads();
    }
}

extern "C" void kernel_launch(void* const* d_in, const int* in_sizes, int n_in,
                              void* d_out, int out_size)
{
    const float* x  = (const float*)d_in[0];
    const float* w1 = (const float*)d_in[1];
    const float* b1 = (const float*)d_in[2];
    const float* w2 = (const float*)d_in[3];
    const float* b2 = (const float*)d_in[4];
    const float* wf = (const float*)d_in[5];
    const float* bf = (const float*)d_in[6];
    float* out = (float*)d_out;

    int nb = in_sizes[0] / 784;   // batch size (4096)
    snn_kernel<<<nb, 192>>>(x, w1, b1, w2, b2, wf, bf, out, nb);
}

// round 2
// speedup vs baseline: 1.0140x; 1.0140x over previous
#include <cuda_runtime.h>

// SpikeCNN fused: one block = one image, all 8 timesteps.
// All hot SMEM accesses are lane-contiguous (1 L1 wavefront per LDS).
// mem1 in registers; conv1 hoisted out of time loop.

#define TH 1.0f
#define TSTEPS 8
#define NT 224
#define XPITCH 33          // xpadT: col*33 + row (col-major)
#define C1CP 30            // c1s: c*840 + col*30 + row (col-major)

__global__ __launch_bounds__(NT, 3)
void snn_kernel(const float* __restrict__ x,
                const float* __restrict__ w1, const float* __restrict__ b1,
                const float* __restrict__ w2, const float* __restrict__ b2,
                const float* __restrict__ wf, const float* __restrict__ bf,
                float* __restrict__ out, int nb)
{
    __shared__ float xpadT[32 * XPITCH];   // 1056: zero-padded input, col-major
    __shared__ float c1s[3 * 28 * C1CP];   // 2520: conv1 output, col-major
    __shared__ float p1[3 * 396];          // 1188: [ic][k(0..10)][r*2+h] duplicated layout
    __shared__ float s2L[6 * 196];         // oc*196 + jj*28 + (row*2+h)
    __shared__ float p2s[294];
    __shared__ float w2s[450];
    __shared__ float fcsum[10], mem3s[10], acc3s[10];

    const int tid  = threadIdx.x;
    const int warp = tid >> 5;             // 0..6
    const int lane = tid & 31;
    const int b    = blockIdx.x;

    // ---- init ----
    for (int i = tid; i < 32 * XPITCH; i += NT) xpadT[i] = 0.f;
    for (int i = tid; i < 3 * 396; i += NT)     p1[i]    = 0.f;
    for (int i = tid; i < 450; i += NT)         w2s[i]   = w2[i];
    if (tid < 10) { mem3s[tid] = 0.f; acc3s[tid] = 0.f; }
    __syncthreads();

    const float* xb = x + (size_t)b * 784;
    for (int i = tid; i < 784; i += NT) {
        int r = i / 28, c = i % 28;
        xpadT[(c + 2) * XPITCH + (r + 2)] = xb[i];
    }
    __syncthreads();

    // ---- conv1 (once): warps 0..5 -> (c = warp%3, colhalf = warp/3), lane = row ----
    if (warp < 6 && lane < 28) {
        int c = warp % 3, colbase = (warp / 3) * 14, row = lane;
        float wr[25];
        #pragma unroll
        for (int k = 0; k < 25; k++) wr[k] = __ldg(&w1[c * 25 + k]);
        float bias = __ldg(&b1[c]);
        float acc[14];
        #pragma unroll
        for (int j = 0; j < 14; j++) acc[j] = bias;
        #pragma unroll
        for (int di = 0; di < 5; di++) {
            float v[18];
            #pragma unroll
            for (int k = 0; k < 18; k++)
                v[k] = xpadT[(colbase + k) * XPITCH + row + di];   // lanes contiguous
            #pragma unroll
            for (int j = 0; j < 14; j++)
                #pragma unroll
                for (int dj = 0; dj < 5; dj++)
                    acc[j] += v[j + dj] * wr[di * 5 + dj];
        }
        #pragma unroll
        for (int j = 0; j < 14; j++)
            c1s[c * 840 + (colbase + j) * C1CP + row] = acc[j];    // lanes contiguous
    }
    __syncthreads();

    // ---- persistent register state ----
    float mr[12];                          // mem1: 3 tasks x 4 cells
    #pragma unroll
    for (int i = 0; i < 12; i++) mr[i] = 0.f;
    float m2r[7];
    #pragma unroll
    for (int j = 0; j < 7; j++) m2r[j] = 0.f;
    const float b2r = (warp < 6 && lane < 28) ? __ldg(&b2[warp]) : 0.f;

    const int  pi   = lane % 14;           // phase-A pooled row
    const int  dpj  = lane / 14;           // 0/1: which column of the pj pair
    const bool aact = (lane < 28);

    // ---- time loop ----
    for (int t = 0; t < TSTEPS; t++) {
        // A: mem1 += c1 (regs + smem), fire, pool -> p1 (duplicated layout)
        if (aact) {
            #pragma unroll
            for (int i = 0; i < 3; i++) {
                int task = warp * 3 + i;               // 0..20
                int c    = task / 7;                   // 0..2
                int pp   = task - 7 * c;               // 0..6
                int pj   = 2 * pp + dpj;               // 0..13
                int base = c * 840 + (2 * pj) * C1CP + 2 * pi;
                float m0 = mr[i * 4 + 0] + c1s[base];
                float m1 = mr[i * 4 + 1] + c1s[base + 1];
                float m2 = mr[i * 4 + 2] + c1s[base + C1CP];
                float m3 = mr[i * 4 + 3] + c1s[base + C1CP + 1];
                float s0 = (m0 >= TH) ? TH : 0.f;
                float s1 = (m1 >= TH) ? TH : 0.f;
                float s2 = (m2 >= TH) ? TH : 0.f;
                float s3 = (m3 >= TH) ? TH : 0.f;
                mr[i * 4 + 0] = m0 - s0;
                mr[i * 4 + 1] = m1 - s1;
                mr[i * 4 + 2] = m2 - s2;
                mr[i * 4 + 3] = m3 - s3;
                float val = 0.25f * (s0 + s1 + s2 + s3);
                int cpad = pj + 2;                     // padded col 2..15
                int pb   = c * 396 + (pi + 2) * 2;
                if (cpad <= 10) p1[pb + cpad * 36]           = val;   // h=0 slot
                if (cpad >= 7)  p1[pb + (cpad - 7) * 36 + 1] = val;   // h=1 slot
            }
        }
        __syncthreads();

        // B: conv2 + mem2 fire. warp = oc (0..5); lane = row*2+h; 7 outputs/thread
        if (warp < 6 && lane < 28) {
            int oc = warp;
            float acc[7];
            #pragma unroll
            for (int j = 0; j < 7; j++) acc[j] = b2r;
            #pragma unroll
            for (int ic = 0; ic < 3; ic++) {
                float wr[25];
                #pragma unroll
                for (int k = 0; k < 25; k++) wr[k] = w2s[oc * 75 + ic * 25 + k];  // broadcast
                #pragma unroll
                for (int di = 0; di < 5; di++) {
                    float v[11];
                    const float* src = &p1[ic * 396 + lane + 2 * di];
                    #pragma unroll
                    for (int k = 0; k < 11; k++) v[k] = src[k * 36];  // lanes contiguous
                    #pragma unroll
                    for (int j = 0; j < 7; j++)
                        #pragma unroll
                        for (int dj = 0; dj < 5; dj++)
                            acc[j] += v[j + dj] * wr[di * 5 + dj];
                }
            }
            float* dst = &s2L[oc * 196 + lane];
            #pragma unroll
            for (int j = 0; j < 7; j++) {
                float m  = m2r[j] + acc[j];
                float sp = (m >= TH) ? TH : 0.f;
                m2r[j]   = m - sp;
                dst[j * 28] = sp;                                    // lanes contiguous
            }
        }
        __syncthreads();

        // C: 2x2 avg-pool layer 2 -> p2 (flatten order oc*49 + po*7 + qo)
        for (int idx = tid; idx < 294; idx += NT) {
            int oc = idx / 49, rem = idx - 49 * oc, po = rem / 7, qo = rem - 7 * po;
            float s = 0.f;
            #pragma unroll
            for (int a = 0; a < 2; a++)
                #pragma unroll
                for (int bb = 0; bb < 2; bb++) {
                    int r  = 2 * po + a, cc = 2 * qo + bb;
                    int h  = (cc >= 7) ? 1 : 0;
                    int jj = cc - 7 * h;
                    s += s2L[oc * 196 + jj * 28 + r * 2 + h];
                }
            p2s[idx] = 0.25f * s;
        }
        __syncthreads();

        // D: fc — warp w reduces row w (and 7+w for w<3)
        {
            float part = 0.f;
            const float* wrow = wf + warp * 294;
            for (int k = lane; k < 294; k += 32) part += p2s[k] * __ldg(&wrow[k]);
            #pragma unroll
            for (int s = 16; s > 0; s >>= 1) part += __shfl_xor_sync(0xffffffffu, part, s);
            if (lane == 0) fcsum[warp] = part;
            if (warp < 3) {
                float part2 = 0.f;
                const float* wrow2 = wf + (7 + warp) * 294;
                for (int k = lane; k < 294; k += 32) part2 += p2s[k] * __ldg(&wrow2[k]);
                #pragma unroll
                for (int s = 16; s > 0; s >>= 1) part2 += __shfl_xor_sync(0xffffffffu, part2, s);
                if (lane == 0) fcsum[7 + warp] = part2;
            }
        }
        __syncthreads();

        // E: mem3 update, fire, accumulate, emit running average at t=3,7
        if (tid < 10) {
            float m  = mem3s[tid] + fcsum[tid] + __ldg(&bf[tid]);
            float sp = (m >= TH) ? TH : 0.f;
            mem3s[tid] = m - sp;
            float a = acc3s[tid] + sp;
            acc3s[tid] = a;
            if (t == 3) out[(size_t)b * 10 + tid] = a * 0.25f;
            if (t == 7) out[(size_t)nb * 10 + (size_t)b * 10 + tid] = a * 0.125f;
        }
        __syncthreads();
    }
}

extern "C" void kernel_launch(void* const* d_in, const int* in_sizes, int n_in,
                              void* d_out, int out_size)
{
    const float* x  = (const float*)d_in[0];
    const float* w1 = (const float*)d_in[1];
    const float* b1 = (const float*)d_in[2];
    const float* w2 = (const float*)d_in[3];
    const float* b2 = (const float*)d_in[4];
    const float* wf = (const float*)d_in[5];
    const float* bf = (const float*)d_in[6];
    float* out = (float*)d_out;

    int nb = in_sizes[0] / 784;   // 4096
    snn_kernel<<<nb, NT>>>(x, w1, b1, w2, b2, wf, bf, out, nb);
}

// round 4
// speedup vs baseline: 1.1429x; 1.1271x over previous
#include <cuda_runtime.h>

// SpikeCNN fused: one block = one image, all 8 timesteps.
// Conv2 inputs/weights laid out for LDS.128 (k-contiguous per thread).
// mem1/mem2 in registers; conv1 hoisted out of time loop.
// All vector-accessed smem arrays are 16B-aligned (R3 fix: misaligned LDS.128).

#define TH 1.0f
#define TSTEPS 8
#define NT 224
#define XPITCH 33          // xpadT: col*33 + row (col-major)
#define C1CP 30            // c1s: c*840 + col*30 + row (col-major)
#define P1P 12             // p1k: [ic][rh(36)][k(12)]  (k 0..10 used)

__global__ __launch_bounds__(NT, 3)
void snn_kernel(const float* __restrict__ x,
                const float* __restrict__ w1, const float* __restrict__ b1,
                const float* __restrict__ w2, const float* __restrict__ b2,
                const float* __restrict__ wf, const float* __restrict__ bf,
                float* __restrict__ out, int nb)
{
    __shared__ __align__(16) float xpadT[32 * XPITCH];    // 1056
    __shared__ __align__(16) float c1s[3 * 28 * C1CP];    // 2520 (col-major)
    __shared__ __align__(16) float p1k[3 * 36 * P1P];     // 1296: [ic][rh][k], pitch 12
    __shared__ __align__(16) float w2p[18 * 28];          // [oc*3+ic][k], stride 28
    __shared__ float s2L[6 * 196];          // oc*196 + j*28 + (row*2+h)
    __shared__ float p2s[294];
    __shared__ float fcsum[10], mem3s[10], acc3s[10];

    const int tid  = threadIdx.x;
    const int warp = tid >> 5;              // 0..6
    const int lane = tid & 31;
    const int b    = blockIdx.x;

    // ---- init ----
    for (int i = tid; i < 32 * XPITCH; i += NT)  xpadT[i] = 0.f;
    for (int i = tid; i < 3 * 36 * P1P; i += NT) p1k[i]   = 0.f;
    for (int i = tid; i < 18 * 28; i += NT)      w2p[i]   = 0.f;
    if (tid < 10) { mem3s[tid] = 0.f; acc3s[tid] = 0.f; }
    __syncthreads();
    for (int i = tid; i < 450; i += NT) {
        int g = i / 25, k = i - 25 * g;
        w2p[g * 28 + k] = w2[i];
    }
    const float* xb = x + (size_t)b * 784;
    for (int i = tid; i < 784; i += NT) {
        int r = i / 28, c = i % 28;
        xpadT[(c + 2) * XPITCH + (r + 2)] = xb[i];
    }
    __syncthreads();

    // ---- conv1 (once): warps 0..5 -> (c = warp%3, colhalf = warp/3), lane = row ----
    if (warp < 6 && lane < 28) {
        int c = warp % 3, colbase = (warp / 3) * 14, row = lane;
        float wr[25];
        #pragma unroll
        for (int k = 0; k < 25; k++) wr[k] = __ldg(&w1[c * 25 + k]);
        float bias = __ldg(&b1[c]);
        float acc[14];
        #pragma unroll
        for (int j = 0; j < 14; j++) acc[j] = bias;
        #pragma unroll
        for (int di = 0; di < 5; di++) {
            float v[18];
            #pragma unroll
            for (int k = 0; k < 18; k++)
                v[k] = xpadT[(colbase + k) * XPITCH + row + di];
            #pragma unroll
            for (int j = 0; j < 14; j++)
                #pragma unroll
                for (int dj = 0; dj < 5; dj++)
                    acc[j] += v[j + dj] * wr[di * 5 + dj];
        }
        #pragma unroll
        for (int j = 0; j < 14; j++)
            c1s[c * 840 + (colbase + j) * C1CP + row] = acc[j];
    }
    __syncthreads();

    // ---- persistent register state ----
    float mr[12];                           // mem1: 3 tasks x 4 cells
    #pragma unroll
    for (int i = 0; i < 12; i++) mr[i] = 0.f;
    float m2r[7];
    #pragma unroll
    for (int j = 0; j < 7; j++) m2r[j] = 0.f;
    const float b2r = (warp < 6 && lane < 28) ? __ldg(&b2[warp]) : 0.f;

    const int  pi   = lane % 14;            // phase-A pooled row
    const int  dpj  = lane / 14;            // 0/1
    const bool aact = (lane < 28);

    // ---- time loop ----
    for (int t = 0; t < TSTEPS; t++) {
        // A: mem1 += c1, fire, pool -> p1k (duplicated k-layout)
        if (aact) {
            #pragma unroll
            for (int i = 0; i < 3; i++) {
                int task = warp * 3 + i;                // 0..20
                int c    = task / 7;
                int pp   = task - 7 * c;
                int pj   = 2 * pp + dpj;
                int base = c * 840 + (2 * pj) * C1CP + 2 * pi;
                float2 ca = *reinterpret_cast<const float2*>(&c1s[base]);
                float2 cb = *reinterpret_cast<const float2*>(&c1s[base + C1CP]);
                float m0 = mr[i * 4 + 0] + ca.x;
                float m1 = mr[i * 4 + 1] + ca.y;
                float m2 = mr[i * 4 + 2] + cb.x;
                float m3 = mr[i * 4 + 3] + cb.y;
                float s0 = (m0 >= TH) ? TH : 0.f;
                float s1 = (m1 >= TH) ? TH : 0.f;
                float s2 = (m2 >= TH) ? TH : 0.f;
                float s3 = (m3 >= TH) ? TH : 0.f;
                mr[i * 4 + 0] = m0 - s0;
                mr[i * 4 + 1] = m1 - s1;
                mr[i * 4 + 2] = m2 - s2;
                mr[i * 4 + 3] = m3 - s3;
                float val = 0.25f * (s0 + s1 + s2 + s3);
                int cpad = pj + 2;                      // 2..15
                int rb   = c * 432 + (pi + 2) * 2 * P1P;
                if (cpad <= 10) p1k[rb + cpad] = val;             // h=0 row
                if (cpad >= 7)  p1k[rb + P1P + (cpad - 7)] = val; // h=1 row
            }
        }
        __syncthreads();

        // B: conv2 + mem2 fire. warp = oc (0..5); lane = row*2+h; 7 outputs/thread
        if (warp < 6 && lane < 28) {
            int oc = warp;
            float acc[7];
            #pragma unroll
            for (int j = 0; j < 7; j++) acc[j] = b2r;
            #pragma unroll
            for (int ic = 0; ic < 3; ic++) {
                float wr[28];
                const float4* wsrc =
                    reinterpret_cast<const float4*>(&w2p[(oc * 3 + ic) * 28]);
                #pragma unroll
                for (int q = 0; q < 7; q++) {
                    float4 w4 = wsrc[q];
                    wr[4 * q] = w4.x; wr[4 * q + 1] = w4.y;
                    wr[4 * q + 2] = w4.z; wr[4 * q + 3] = w4.w;
                }
                #pragma unroll
                for (int di = 0; di < 5; di++) {
                    const float4* srcv = reinterpret_cast<const float4*>(
                        &p1k[ic * 432 + (lane + 2 * di) * P1P]);
                    float4 A0 = srcv[0], A1 = srcv[1], A2 = srcv[2];
                    float v[11] = {A0.x, A0.y, A0.z, A0.w,
                                   A1.x, A1.y, A1.z, A1.w,
                                   A2.x, A2.y, A2.z};
                    #pragma unroll
                    for (int j = 0; j < 7; j++)
                        #pragma unroll
                        for (int dj = 0; dj < 5; dj++)
                            acc[j] += v[j + dj] * wr[di * 5 + dj];
                }
            }
            float* dst = &s2L[oc * 196 + lane];
            #pragma unroll
            for (int j = 0; j < 7; j++) {
                float m  = m2r[j] + acc[j];
                float sp = (m >= TH) ? TH : 0.f;
                m2r[j]   = m - sp;
                dst[j * 28] = sp;
            }
        }
        __syncthreads();

        // C: 2x2 avg-pool layer 2 -> p2 (flatten order oc*49 + po*7 + qo)
        for (int idx = tid; idx < 294; idx += NT) {
            int oc = idx / 49, rem = idx - 49 * oc, po = rem / 7, qo = rem - 7 * po;
            float s = 0.f;
            #pragma unroll
            for (int a = 0; a < 2; a++)
                #pragma unroll
                for (int bb = 0; bb < 2; bb++) {
                    int r  = 2 * po + a, cc = 2 * qo + bb;
                    int h  = (cc >= 7) ? 1 : 0;
                    int jj = cc - 7 * h;
                    s += s2L[oc * 196 + jj * 28 + r * 2 + h];
                }
            p2s[idx] = 0.25f * s;
        }
        __syncthreads();

        // D: fc — warp w reduces row w (and 7+w for w<3)
        {
            float part = 0.f;
            const float* wrow = wf + warp * 294;
            for (int k = lane; k < 294; k += 32) part += p2s[k] * __ldg(&wrow[k]);
            #pragma unroll
            for (int s = 16; s > 0; s >>= 1) part += __shfl_xor_sync(0xffffffffu, part, s);
            if (lane == 0) fcsum[warp] = part;
            if (warp < 3) {
                float part2 = 0.f;
                const float* wrow2 = wf + (7 + warp) * 294;
                for (int k = lane; k < 294; k += 32) part2 += p2s[k] * __ldg(&wrow2[k]);
                #pragma unroll
                for (int s = 16; s > 0; s >>= 1) part2 += __shfl_xor_sync(0xffffffffu, part2, s);
                if (lane == 0) fcsum[7 + warp] = part2;
            }
        }
        __syncthreads();

        // E: mem3 update, fire, accumulate, emit running average at t=3,7
        if (tid < 10) {
            float m  = mem3s[tid] + fcsum[tid] + __ldg(&bf[tid]);
            float sp = (m >= TH) ? TH : 0.f;
            mem3s[tid] = m - sp;
            float a = acc3s[tid] + sp;
            acc3s[tid] = a;
            if (t == 3) out[(size_t)b * 10 + tid] = a * 0.25f;
            if (t == 7) out[(size_t)nb * 10 + (size_t)b * 10 + tid] = a * 0.125f;
        }
        __syncthreads();
    }
}

extern "C" void kernel_launch(void* const* d_in, const int* in_sizes, int n_in,
                              void* d_out, int out_size)
{
    const float* x  = (const float*)d_in[0];
    const float* w1 = (const float*)d_in[1];
    const float* b1 = (const float*)d_in[2];
    const float* w2 = (const float*)d_in[3];
    const float* b2 = (const float*)d_in[4];
    const float* wf = (const float*)d_in[5];
    const float* bf = (const float*)d_in[6];
    float* out = (float*)d_out;

    int nb = in_sizes[0] / 784;   // 4096
    snn_kernel<<<nb, NT>>>(x, w1, b1, w2, b2, wf, bf, out, nb);
}